// round 5
// baseline (speedup 1.0000x reference)
#include <cuda_runtime.h>
#include <math.h>

#define RUNS 512
#define WAYS 5
#define SHOT 5
#define NSUP 25
#define NQ   75
#define N100 100
#define N105 105
#define DIM  640
#define LAMv 10.0f
#define EPSV 0.001f
#define APAD 106
#define TP   113
#define MAXIT 1000

__device__ float g_feat[(size_t)RUNS*N105*DIM];
__device__ float g_proto[(size_t)RUNS*WAYS*DIM];
__device__ float g_M[(size_t)RUNS*NQ*WAYS];
__device__ float g_Z[(size_t)RUNS*N105*WAYS];
__device__ int   g_T[8];
__device__ int   g_bad[6*1024];

__device__ __forceinline__ float wredSum(float v){
    #pragma unroll
    for (int o=16;o;o>>=1) v += __shfl_xor_sync(0xffffffffu, v, o);
    return v;
}
__device__ __forceinline__ float wredMax(float v){
    #pragma unroll
    for (int o=16;o;o>>=1) v = fmaxf(v, __shfl_xor_sync(0xffffffffu, v, o));
    return v;
}

// ---- K0: copy features, initial prototypes, reset T/bad ----
__global__ void __launch_bounds__(256) k_init(const float* __restrict__ xs,
                                              const float* __restrict__ xq){
    int b = blockIdx.x, tid = threadIdx.x;
    if (b==0){
        if (tid<8) g_T[tid]=0;
        for (int t=tid; t<6*1024; t+=256) g_bad[t]=0;
    }
    float* fb = g_feat + (size_t)b*N105*DIM;
    const float* s0 = xs + (size_t)b*NSUP*DIM;
    const float* s1 = xq + (size_t)b*NQ*DIM;
    float4* dst = (float4*)fb;
    const float4* a0 = (const float4*)s0;
    const float4* a1 = (const float4*)s1;
    const int n0 = NSUP*DIM/4, n1 = NQ*DIM/4;
    for (int t=tid; t<n0; t+=256) dst[t] = a0[t];
    for (int t=tid; t<n1; t+=256) dst[n0+t] = a1[t];
    float* pr = g_proto + (size_t)b*WAYS*DIM;
    for (int t=tid; t<WAYS*DIM; t+=256){
        int w = t/DIM, d = t-w*DIM;
        float a = 0.f;
        #pragma unroll
        for (int s=0;s<SHOT;s++) a += s0[(w*SHOT+s)*DIM + d];
        pr[t] = a*0.2f;
    }
}

// ---- K1: M = exp(-lam * d2(queries, proto)) ----
__global__ void __launch_bounds__(256) k_dist_proto(){
    __shared__ float sp[WAYS*DIM];
    __shared__ float pn[WAYS];
    int b = blockIdx.x, tid = threadIdx.x;
    const float* pr = g_proto + (size_t)b*WAYS*DIM;
    for (int t=tid; t<WAYS*DIM; t+=256) sp[t] = pr[t];
    __syncthreads();
    int w = tid>>5, lane = tid&31;
    if (w < WAYS){
        float a=0.f;
        for (int d=lane; d<DIM; d+=32){ float v=sp[w*DIM+d]; a += v*v; }
        a = wredSum(a);
        if (lane==0) pn[w]=a;
    }
    __syncthreads();
    const float* fb = g_feat + (size_t)b*N105*DIM;
    for (int r=w; r<NQ; r+=8){
        const float* f = fb + (size_t)(NSUP+r)*DIM;
        float nf=0.f, dk[WAYS]={0,0,0,0,0};
        for (int d=lane; d<DIM; d+=32){
            float v = f[d];
            nf += v*v;
            #pragma unroll
            for (int k=0;k<WAYS;k++) dk[k] += v*sp[k*DIM+d];
        }
        nf = wredSum(nf);
        #pragma unroll
        for (int k=0;k<WAYS;k++) dk[k] = wredSum(dk[k]);
        if (lane < WAYS){
            float d2 = fmaxf(nf + pn[lane] - 2.0f*dk[lane], 0.0f);
            g_M[((size_t)b*NQ + r)*WAYS + lane] = expf(-LAMv*d2);
        }
    }
}

// ---- Sinkhorn, warp per run. phaseB=0: mark bad iters; 1: apply T ----
template<int N, int NL>
__global__ void __launch_bounds__(256) k_sinkhorn(const int* __restrict__ ys,
                                                  int slot, int phaseB){
    const int gw = (blockIdx.x*blockDim.x + threadIdx.x) >> 5;
    const int lane = threadIdx.x & 31;
    if (gw >= RUNS) return;
    const int b = gw;
    constexpr int J = (N+31)/32;
    const float cval = (float)(N/WAYS);
    const float* in; float* out;
    if (N == NQ){ in = g_M + (size_t)b*NQ*WAYS;   out = g_Z + ((size_t)b*N105 + NSUP)*WAYS; }
    else        { in = g_Z + (size_t)b*N105*WAYS; out = g_Z + (size_t)b*N105*WAYS; }
    float p[J][WAYS];
    bool valid[J];
    #pragma unroll
    for (int j=0;j<J;j++){
        int r = lane + 32*j;
        valid[j] = (r < N);
        #pragma unroll
        for (int k=0;k<WAYS;k++) p[j][k] = valid[j] ? in[r*WAYS+k] : 0.0f;
    }
    int ycls = 0;
    const bool pin = (NL>0) && (lane < NL);
    if (pin) ycls = ys[b*NSUP + lane];

    if (!phaseB){
        float u[J];
        #pragma unroll
        for (int j=0;j<J;j++) u[j]=0.0f;
        int streak = 0;
        int* badp = g_bad + slot*1024;
        for (int t=0; t<MAXIT; t++){
            float rs[J]; float dv = 0.0f;
            #pragma unroll
            for (int j=0;j<J;j++){
                rs[j] = p[j][0]+p[j][1]+p[j][2]+p[j][3]+p[j][4];
                if (valid[j]) dv = fmaxf(dv, fabsf(u[j]-rs[j]));
            }
            dv = wredMax(dv);
            if (dv > EPSV){ if (lane==0) badp[t] = 1; streak = 0; }
            else if (++streak >= 12) break;
            #pragma unroll
            for (int j=0;j<J;j++){
                u[j] = rs[j];
                if (valid[j]){
                    float f = 1.0f/rs[j];
                    #pragma unroll
                    for (int k=0;k<WAYS;k++) p[j][k] *= f;
                }
            }
            #pragma unroll
            for (int k=0;k<WAYS;k++){
                float a = 0.0f;
                #pragma unroll
                for (int j=0;j<J;j++) if (valid[j]) a += p[j][k];
                float f = cval/wredSum(a);
                #pragma unroll
                for (int j=0;j<J;j++) if (valid[j]) p[j][k] *= f;
            }
            if (pin){
                #pragma unroll
                for (int k=0;k<WAYS;k++) p[0][k] = (k==ycls)?1.0f:0.0f;
            }
        }
    } else {
        const int T = g_T[slot];
        for (int t=0; t<T; t++){
            #pragma unroll
            for (int j=0;j<J;j++){
                float rs = p[j][0]+p[j][1]+p[j][2]+p[j][3]+p[j][4];
                if (valid[j]){
                    float f = 1.0f/rs;
                    #pragma unroll
                    for (int k=0;k<WAYS;k++) p[j][k] *= f;
                }
            }
            #pragma unroll
            for (int k=0;k<WAYS;k++){
                float a = 0.0f;
                #pragma unroll
                for (int j=0;j<J;j++) if (valid[j]) a += p[j][k];
                float f = cval/wredSum(a);
                #pragma unroll
                for (int j=0;j<J;j++) if (valid[j]) p[j][k] *= f;
            }
            if (pin){
                #pragma unroll
                for (int k=0;k<WAYS;k++) p[0][k] = (k==ycls)?1.0f:0.0f;
            }
        }
        #pragma unroll
        for (int j=0;j<J;j++) if (valid[j]){
            int r = lane + 32*j;
            #pragma unroll
            for (int k=0;k<WAYS;k++) out[r*WAYS+k] = p[j][k];
        }
    }
}

// ---- scan: T = first t with no run bad (exact while_loop stop) ----
__global__ void __launch_bounds__(256) k_scan(int slot){
    __shared__ int mn[256];
    int tid = threadIdx.x;
    const int* badp = g_bad + slot*1024;
    int best = MAXIT;
    for (int t=tid; t<MAXIT; t+=256) if (badp[t]==0 && t<best) best = t;
    mn[tid] = best;
    __syncthreads();
    for (int s=128; s; s>>=1){ if (tid<s) mn[tid] = min(mn[tid], mn[tid+s]); __syncthreads(); }
    if (tid==0) g_T[slot] = mn[0];
}

// ---- K3: entropy weighting, proto update, mask, write appended rows ----
__global__ void __launch_bounds__(256) k_update(const int* __restrict__ ys){
    __shared__ float z[N100][WAYS];
    __shared__ float ent[N100];
    __shared__ float S[WAYS];
    __shared__ float sp[WAYS*DIM];
    __shared__ float dpd[WAYS*WAYS];
    __shared__ float dpe[WAYS*WAYS];
    __shared__ float maskv[WAYS];
    __shared__ float omega_s;
    int b = blockIdx.x, tid = threadIdx.x;
    float* Zb = g_Z + (size_t)b*N105*WAYS;
    const float INVLOG5 = 0.6213349345596119f;
    if (tid < N100){
        if (tid < NSUP){
            int c = ys[b*NSUP + tid];
            #pragma unroll
            for (int k=0;k<WAYS;k++) z[tid][k] = (k==c)?1.0f:0.0f;
        } else {
            #pragma unroll
            for (int k=0;k<WAYS;k++) z[tid][k] = Zb[tid*WAYS+k];
        }
        float q[WAYS]; float s = 0.0f;
        #pragma unroll
        for (int k=0;k<WAYS;k++){ q[k] = z[tid][k] + 1e-12f; s += q[k]; }
        float H = 0.0f;
        #pragma unroll
        for (int k=0;k<WAYS;k++){ float pp = q[k]/s; H -= pp*logf(pp); }
        float e = H*INVLOG5;
        ent[tid] = e;
        float wgt = 1.0f - e;
        #pragma unroll
        for (int k=0;k<WAYS;k++) z[tid][k] *= wgt;
    }
    __syncthreads();
    if (tid < WAYS){
        float a = 0.0f;
        for (int i=0;i<N100;i++) a += z[i][tid];
        S[tid] = a;
    }
    if (tid == 128){
        float a = 0.0f;
        for (int i=0;i<N100;i++) a += ent[i];
        omega_s = a*0.01f;
    }
    __syncthreads();
    const float* fb = g_feat + (size_t)b*N105*DIM;
    float* prb = g_proto + (size_t)b*WAYS*DIM;
    for (int d=tid; d<DIM; d+=256){
        float acc[WAYS] = {0,0,0,0,0};
        for (int i=0;i<N100;i++){
            float f = fb[(size_t)i*DIM + d];
            #pragma unroll
            for (int k=0;k<WAYS;k++) acc[k] += z[i][k]*f;
        }
        #pragma unroll
        for (int k=0;k<WAYS;k++){
            float pv = 0.4f*prb[k*DIM+d] + 0.6f*(acc[k]/S[k]);
            prb[k*DIM+d] = pv;
            sp[k*DIM+d]  = pv;
        }
    }
    __syncthreads();
    int w = tid>>5, lane = tid&31;
    for (int pidx=w; pidx<WAYS*WAYS; pidx+=8){
        int a = pidx/WAYS, c = pidx%WAYS;
        float acc = 0.0f;
        for (int d=lane; d<DIM; d+=32) acc += sp[a*DIM+d]*sp[c*DIM+d];
        acc = wredSum(acc);
        if (lane==0) dpd[pidx] = acc;
    }
    __syncthreads();
    if (tid < WAYS*WAYS){
        int a = tid/WAYS, c = tid%WAYS;
        float d2 = fmaxf(dpd[a*WAYS+a] + dpd[c*WAYS+c] - 2.0f*dpd[tid], 0.0f);
        dpe[tid] = expf(-LAMv*d2);
    }
    __syncthreads();
    if (tid < WAYS){
        float q[WAYS]; float s = 0.0f;
        #pragma unroll
        for (int k=0;k<WAYS;k++){ q[k] = dpe[tid*WAYS+k] + 1e-12f; s += q[k]; }
        float H = 0.0f;
        #pragma unroll
        for (int k=0;k<WAYS;k++){ float pp = q[k]/s; H -= pp*logf(pp); }
        maskv[tid] = (H*INVLOG5 < omega_s) ? 1.0f : 0.0f;
    }
    __syncthreads();
    float* fwr = g_feat + (size_t)b*N105*DIM + (size_t)N100*DIM;
    for (int t=tid; t<WAYS*DIM; t+=256) fwr[t] = sp[t]*maskv[t/DIM];
    for (int t=tid; t<N100*WAYS; t+=256) Zb[t] = z[t/WAYS][t%WAYS];
    if (tid < WAYS*WAYS) Zb[N100*WAYS + tid] = dpe[tid]*maskv[tid/WAYS];
}

// ---- K4: Gram -> W -> A=I-aW -> LU solve (A X = Z) ----
__global__ void __launch_bounds__(256,2) k_graph_solve(){
    __shared__ float As[N105*APAD];
    __shared__ float zz[N105*WAYS];
    __shared__ float nn[N105];
    __shared__ float dm[N105];
    int b = blockIdx.x, tid = threadIdx.x;
    int tx = tid & 15, ty = tid >> 4;
    const float* fb = g_feat + (size_t)b*N105*DIM;
    float acc[7][7];
    #pragma unroll
    for (int i=0;i<7;i++)
        #pragma unroll
        for (int j=0;j<7;j++) acc[i][j]=0.0f;

    float* tile = As; // [64][113] transposed chunk
    for (int c=0;c<10;c++){
        for (int t=tid; t<N105*64; t+=256){
            int row = t>>6, k = t&63;
            tile[k*TP+row] = fb[(size_t)row*DIM + c*64 + k];
        }
        for (int t=tid; t<64*7; t+=256) tile[(t/7)*TP + 105 + (t%7)] = 0.0f;
        __syncthreads();
        #pragma unroll 4
        for (int k=0;k<64;k++){
            float av[7], bv[7];
            #pragma unroll
            for (int e=0;e<7;e++){ av[e]=tile[k*TP+ty+16*e]; bv[e]=tile[k*TP+tx+16*e]; }
            #pragma unroll
            for (int i=0;i<7;i++)
                #pragma unroll
                for (int j=0;j<7;j++) acc[i][j] += av[i]*bv[j];
        }
        __syncthreads();
    }
    #pragma unroll
    for (int i=0;i<7;i++){
        int r = ty + 16*i;
        if (r < N105){
            #pragma unroll
            for (int j=0;j<7;j++){
                int cc = tx + 16*j;
                if (cc < N105) As[r*APAD+cc] = acc[i][j];
            }
        }
    }
    float* Zb = g_Z + (size_t)b*N105*WAYS;
    for (int t=tid; t<N105*WAYS; t+=256) zz[t] = Zb[t];
    __syncthreads();
    if (tid < N105) nn[tid] = As[tid*APAD+tid];
    __syncthreads();
    for (int t=tid; t<N105*N105; t+=256){
        int i=t/N105, j=t-i*N105;
        float g = As[i*APAD+j];
        float d2 = fmaxf(nn[i]+nn[j]-2.0f*g, 0.0f);
        As[i*APAD+j] = (i==j) ? 0.0f : expf(-LAMv*d2);
    }
    __syncthreads();
    if (tid < N105){
        float s = 0.0f;
        for (int j=0;j<N105;j++) s += As[tid*APAD+j];
        dm[tid] = rsqrtf(s);
    }
    __syncthreads();
    for (int t=tid; t<N105*N105; t+=256){
        int i=t/N105, j=t-i*N105;
        float w = 0.7f*dm[i]*dm[j]*As[i*APAD+j];
        As[i*APAD+j] = ((i==j)?1.0f:0.0f) - w;
    }
    __syncthreads();
    for (int k=0;k<N105-1;k++){
        int i = k+1+tid;
        if (i < N105){
            float f = As[i*APAD+k]/As[k*APAD+k];
            for (int j=k+1;j<N105;j++) As[i*APAD+j] -= f*As[k*APAD+j];
            #pragma unroll
            for (int m=0;m<WAYS;m++) zz[i*WAYS+m] -= f*zz[k*WAYS+m];
        }
        __syncthreads();
    }
    for (int k=N105-1;k>=0;k--){
        if (tid < WAYS) zz[k*WAYS+tid] /= As[k*APAD+k];
        __syncthreads();
        for (int t=tid; t<k*WAYS; t+=256){
            int i=t/WAYS, m=t-i*WAYS;
            zz[i*WAYS+m] -= As[i*APAD+k]*zz[k*WAYS+m];
        }
        __syncthreads();
    }
    for (int t=tid; t<N105*WAYS; t+=256) Zb[t] = zz[t];
}

// ---- K5: accuracy over queries ----
__global__ void __launch_bounds__(128) k_acc(const int* __restrict__ yq, float* __restrict__ out){
    __shared__ int cnt[128];
    int b = blockIdx.x, tid = threadIdx.x;
    int m = 0;
    if (tid < NQ){
        const float* zr = g_Z + ((size_t)b*N105 + NSUP + tid)*WAYS;
        float best = zr[0]; int bi = 0;
        #pragma unroll
        for (int k=1;k<WAYS;k++){ if (zr[k] > best){ best = zr[k]; bi = k; } }
        m = (bi == yq[b*NQ + tid]) ? 1 : 0;
    }
    cnt[tid] = m;
    __syncthreads();
    for (int s=64; s; s>>=1){ if (tid < s) cnt[tid] += cnt[tid+s]; __syncthreads(); }
    if (tid==0) out[b] = (float)cnt[0] / 75.0f;
}

extern "C" void kernel_launch(void* const* d_in, const int* in_sizes, int n_in,
                              void* d_out, int out_size){
    const float* xs = (const float*)d_in[0];
    const float* xq = (const float*)d_in[1];
    const int*   ys = (const int*)d_in[2];
    const int*   yq = (const int*)d_in[3];
    float* out = (float*)d_out;
    (void)in_sizes; (void)n_in; (void)out_size;

    k_init<<<RUNS,256>>>(xs, xq);
    for (int e=0;e<3;e++){
        k_dist_proto<<<RUNS,256>>>();
        k_sinkhorn<NQ,0><<<64,256>>>(ys, 2*e, 0);
        k_scan<<<1,256>>>(2*e);
        k_sinkhorn<NQ,0><<<64,256>>>(ys, 2*e, 1);
        k_update<<<RUNS,256>>>(ys);
        k_graph_solve<<<RUNS,256>>>();
        k_sinkhorn<N105,NSUP><<<64,256>>>(ys, 2*e+1, 0);
        k_scan<<<1,256>>>(2*e+1);
        k_sinkhorn<N105,NSUP><<<64,256>>>(ys, 2*e+1, 1);
    }
    k_acc<<<RUNS,128>>>(yq, out);
}

// round 6
// speedup vs baseline: 1.4925x; 1.4925x over previous
#include <cuda_runtime.h>
#include <math.h>

#define RUNS 512
#define WAYS 5
#define SHOT 5
#define NSUP 25
#define NQ   75
#define N100 100
#define N105 105
#define DIM  640
#define LAMv 10.0f
#define EPSV 0.001f
#define TP   113
#define MAXIT 1000

__device__ float g_feat[(size_t)RUNS*N105*DIM];
__device__ float g_proto[(size_t)RUNS*WAYS*DIM];
__device__ float g_M[(size_t)RUNS*NQ*WAYS];
__device__ float g_Z[(size_t)RUNS*N105*WAYS];
__device__ float g_E100[(size_t)RUNS*N100*N100];
__device__ int   g_T[8];
__device__ int   g_bad[6*1024];

__device__ __forceinline__ float wredSum(float v){
    #pragma unroll
    for (int o=16;o;o>>=1) v += __shfl_xor_sync(0xffffffffu, v, o);
    return v;
}
__device__ __forceinline__ float wredMax(float v){
    #pragma unroll
    for (int o=16;o;o>>=1) v = fmaxf(v, __shfl_xor_sync(0xffffffffu, v, o));
    return v;
}

// ---- K0: copy features, initial prototypes, reset T/bad ----
__global__ void __launch_bounds__(256) k_init(const float* __restrict__ xs,
                                              const float* __restrict__ xq){
    int b = blockIdx.x, tid = threadIdx.x;
    if (b==0){
        if (tid<8) g_T[tid]=0;
        for (int t=tid; t<6*1024; t+=256) g_bad[t]=0;
    }
    float* fb = g_feat + (size_t)b*N105*DIM;
    const float* s0 = xs + (size_t)b*NSUP*DIM;
    const float* s1 = xq + (size_t)b*NQ*DIM;
    float4* dst = (float4*)fb;
    const float4* a0 = (const float4*)s0;
    const float4* a1 = (const float4*)s1;
    const int n0 = NSUP*DIM/4, n1 = NQ*DIM/4;
    for (int t=tid; t<n0; t+=256) dst[t] = a0[t];
    for (int t=tid; t<n1; t+=256) dst[n0+t] = a1[t];
    float* pr = g_proto + (size_t)b*WAYS*DIM;
    for (int t=tid; t<WAYS*DIM; t+=256){
        int w = t/DIM, d = t-w*DIM;
        float a = 0.f;
        #pragma unroll
        for (int s=0;s<SHOT;s++) a += s0[(w*SHOT+s)*DIM + d];
        pr[t] = a*0.2f;
    }
}

// ---- K0b: one-time 100x100 exp(-lam*d2) block cache ----
__global__ void __launch_bounds__(256) k_gram0(){
    __shared__ float tile[64*TP];
    __shared__ float nd[112];
    int b = blockIdx.x, tid = threadIdx.x;
    int tx = tid & 15, ty = tid >> 4;
    const float* fb = g_feat + (size_t)b*N105*DIM;
    float acc[7][7];
    #pragma unroll
    for (int i=0;i<7;i++)
        #pragma unroll
        for (int j=0;j<7;j++) acc[i][j]=0.0f;
    for (int c=0;c<10;c++){
        for (int t=tid; t<N100*64; t+=256){
            int row = t>>6, k = t&63;
            tile[k*TP+row] = fb[(size_t)row*DIM + c*64 + k];
        }
        for (int t=tid; t<64*13; t+=256) tile[(t/13)*TP + 100 + (t%13)] = 0.0f;
        __syncthreads();
        #pragma unroll 4
        for (int k=0;k<64;k++){
            float av[7], bv[7];
            #pragma unroll
            for (int e=0;e<7;e++){ av[e]=tile[k*TP+ty+16*e]; bv[e]=tile[k*TP+tx+16*e]; }
            #pragma unroll
            for (int i=0;i<7;i++)
                #pragma unroll
                for (int j=0;j<7;j++) acc[i][j] += av[i]*bv[j];
        }
        __syncthreads();
    }
    if (tx==ty){
        #pragma unroll
        for (int e=0;e<7;e++) nd[ty+16*e] = acc[e][e];
    }
    __syncthreads();
    float* E = g_E100 + (size_t)b*N100*N100;
    #pragma unroll
    for (int i=0;i<7;i++){
        int r = ty + 16*i;
        if (r < N100){
            #pragma unroll
            for (int j=0;j<7;j++){
                int c = tx + 16*j;
                if (c < N100){
                    float d2 = fmaxf(nd[r]+nd[c]-2.0f*acc[i][j], 0.0f);
                    E[r*N100+c] = (r==c) ? 0.0f : expf(-LAMv*d2);
                }
            }
        }
    }
}

// ---- K1: M = exp(-lam * d2(queries, proto)) ----
__global__ void __launch_bounds__(256) k_dist_proto(){
    __shared__ float sp[WAYS*DIM];
    __shared__ float pn[WAYS];
    int b = blockIdx.x, tid = threadIdx.x;
    const float* pr = g_proto + (size_t)b*WAYS*DIM;
    for (int t=tid; t<WAYS*DIM; t+=256) sp[t] = pr[t];
    __syncthreads();
    int w = tid>>5, lane = tid&31;
    if (w < WAYS){
        float a=0.f;
        for (int d=lane; d<DIM; d+=32){ float v=sp[w*DIM+d]; a += v*v; }
        a = wredSum(a);
        if (lane==0) pn[w]=a;
    }
    __syncthreads();
    const float* fb = g_feat + (size_t)b*N105*DIM;
    for (int r=w; r<NQ; r+=8){
        const float* f = fb + (size_t)(NSUP+r)*DIM;
        float nf=0.f, dk[WAYS]={0,0,0,0,0};
        for (int d=lane; d<DIM; d+=32){
            float v = f[d];
            nf += v*v;
            #pragma unroll
            for (int k=0;k<WAYS;k++) dk[k] += v*sp[k*DIM+d];
        }
        nf = wredSum(nf);
        #pragma unroll
        for (int k=0;k<WAYS;k++) dk[k] = wredSum(dk[k]);
        if (lane < WAYS){
            float d2 = fmaxf(nf + pn[lane] - 2.0f*dk[lane], 0.0f);
            g_M[((size_t)b*NQ + r)*WAYS + lane] = expf(-LAMv*d2);
        }
    }
}

// ---- Sinkhorn, warp per run. phaseB=0: mark bad iters; 1: apply T ----
template<int N, int NL>
__global__ void __launch_bounds__(256) k_sinkhorn(const int* __restrict__ ys,
                                                  int slot, int phaseB){
    const int gw = (blockIdx.x*blockDim.x + threadIdx.x) >> 5;
    const int lane = threadIdx.x & 31;
    if (gw >= RUNS) return;
    const int b = gw;
    constexpr int J = (N+31)/32;
    const float cval = (float)(N/WAYS);
    const float* in; float* out;
    if (N == NQ){ in = g_M + (size_t)b*NQ*WAYS;   out = g_Z + ((size_t)b*N105 + NSUP)*WAYS; }
    else        { in = g_Z + (size_t)b*N105*WAYS; out = g_Z + (size_t)b*N105*WAYS; }
    float p[J][WAYS];
    bool valid[J];
    #pragma unroll
    for (int j=0;j<J;j++){
        int r = lane + 32*j;
        valid[j] = (r < N);
        #pragma unroll
        for (int k=0;k<WAYS;k++) p[j][k] = valid[j] ? in[r*WAYS+k] : 0.0f;
    }
    int ycls = 0;
    const bool pin = (NL>0) && (lane < NL);
    if (pin) ycls = ys[b*NSUP + lane];

    if (!phaseB){
        float u[J];
        #pragma unroll
        for (int j=0;j<J;j++) u[j]=0.0f;
        int streak = 0;
        int* badp = g_bad + slot*1024;
        for (int t=0; t<MAXIT; t++){
            float rs[J]; float dv = 0.0f;
            #pragma unroll
            for (int j=0;j<J;j++){
                rs[j] = p[j][0]+p[j][1]+p[j][2]+p[j][3]+p[j][4];
                if (valid[j]) dv = fmaxf(dv, fabsf(u[j]-rs[j]));
            }
            dv = wredMax(dv);
            if (dv > EPSV){ if (lane==0) badp[t] = 1; streak = 0; }
            else if (++streak >= 12) break;
            #pragma unroll
            for (int j=0;j<J;j++){
                u[j] = rs[j];
                if (valid[j]){
                    float f = 1.0f/rs[j];
                    #pragma unroll
                    for (int k=0;k<WAYS;k++) p[j][k] *= f;
                }
            }
            #pragma unroll
            for (int k=0;k<WAYS;k++){
                float a = 0.0f;
                #pragma unroll
                for (int j=0;j<J;j++) if (valid[j]) a += p[j][k];
                float f = cval/wredSum(a);
                #pragma unroll
                for (int j=0;j<J;j++) if (valid[j]) p[j][k] *= f;
            }
            if (pin){
                #pragma unroll
                for (int k=0;k<WAYS;k++) p[0][k] = (k==ycls)?1.0f:0.0f;
            }
        }
    } else {
        const int T = g_T[slot];
        for (int t=0; t<T; t++){
            #pragma unroll
            for (int j=0;j<J;j++){
                float rs = p[j][0]+p[j][1]+p[j][2]+p[j][3]+p[j][4];
                if (valid[j]){
                    float f = 1.0f/rs;
                    #pragma unroll
                    for (int k=0;k<WAYS;k++) p[j][k] *= f;
                }
            }
            #pragma unroll
            for (int k=0;k<WAYS;k++){
                float a = 0.0f;
                #pragma unroll
                for (int j=0;j<J;j++) if (valid[j]) a += p[j][k];
                float f = cval/wredSum(a);
                #pragma unroll
                for (int j=0;j<J;j++) if (valid[j]) p[j][k] *= f;
            }
            if (pin){
                #pragma unroll
                for (int k=0;k<WAYS;k++) p[0][k] = (k==ycls)?1.0f:0.0f;
            }
        }
        #pragma unroll
        for (int j=0;j<J;j++) if (valid[j]){
            int r = lane + 32*j;
            #pragma unroll
            for (int k=0;k<WAYS;k++) out[r*WAYS+k] = p[j][k];
        }
    }
}

// ---- scan: T = first t with no run bad (exact while_loop stop) ----
__global__ void __launch_bounds__(256) k_scan(int slot){
    __shared__ int mn[256];
    int tid = threadIdx.x;
    const int* badp = g_bad + slot*1024;
    int best = MAXIT;
    for (int t=tid; t<MAXIT; t+=256) if (badp[t]==0 && t<best) best = t;
    mn[tid] = best;
    __syncthreads();
    for (int s=128; s; s>>=1){ if (tid<s) mn[tid] = min(mn[tid], mn[tid+s]); __syncthreads(); }
    if (tid==0) g_T[slot] = mn[0];
}

// ---- K3: entropy weighting, proto update, mask, write appended rows ----
__global__ void __launch_bounds__(256) k_update(const int* __restrict__ ys){
    __shared__ float z[N100][WAYS];
    __shared__ float ent[N100];
    __shared__ float S[WAYS];
    __shared__ float sp[WAYS*DIM];
    __shared__ float dpd[WAYS*WAYS];
    __shared__ float dpe[WAYS*WAYS];
    __shared__ float maskv[WAYS];
    __shared__ float omega_s;
    int b = blockIdx.x, tid = threadIdx.x;
    float* Zb = g_Z + (size_t)b*N105*WAYS;
    const float INVLOG5 = 0.6213349345596119f;
    if (tid < N100){
        if (tid < NSUP){
            int c = ys[b*NSUP + tid];
            #pragma unroll
            for (int k=0;k<WAYS;k++) z[tid][k] = (k==c)?1.0f:0.0f;
        } else {
            #pragma unroll
            for (int k=0;k<WAYS;k++) z[tid][k] = Zb[tid*WAYS+k];
        }
        float q[WAYS]; float s = 0.0f;
        #pragma unroll
        for (int k=0;k<WAYS;k++){ q[k] = z[tid][k] + 1e-12f; s += q[k]; }
        float H = 0.0f;
        #pragma unroll
        for (int k=0;k<WAYS;k++){ float pp = q[k]/s; H -= pp*logf(pp); }
        float e = H*INVLOG5;
        ent[tid] = e;
        float wgt = 1.0f - e;
        #pragma unroll
        for (int k=0;k<WAYS;k++) z[tid][k] *= wgt;
    }
    __syncthreads();
    if (tid < WAYS){
        float a = 0.0f;
        for (int i=0;i<N100;i++) a += z[i][tid];
        S[tid] = a;
    }
    if (tid == 128){
        float a = 0.0f;
        for (int i=0;i<N100;i++) a += ent[i];
        omega_s = a*0.01f;
    }
    __syncthreads();
    const float* fb = g_feat + (size_t)b*N105*DIM;
    float* prb = g_proto + (size_t)b*WAYS*DIM;
    for (int d=tid; d<DIM; d+=256){
        float acc[WAYS] = {0,0,0,0,0};
        for (int i=0;i<N100;i++){
            float f = fb[(size_t)i*DIM + d];
            #pragma unroll
            for (int k=0;k<WAYS;k++) acc[k] += z[i][k]*f;
        }
        #pragma unroll
        for (int k=0;k<WAYS;k++){
            float pv = 0.4f*prb[k*DIM+d] + 0.6f*(acc[k]/S[k]);
            prb[k*DIM+d] = pv;
            sp[k*DIM+d]  = pv;
        }
    }
    __syncthreads();
    int w = tid>>5, lane = tid&31;
    for (int pidx=w; pidx<WAYS*WAYS; pidx+=8){
        int a = pidx/WAYS, c = pidx%WAYS;
        float acc = 0.0f;
        for (int d=lane; d<DIM; d+=32) acc += sp[a*DIM+d]*sp[c*DIM+d];
        acc = wredSum(acc);
        if (lane==0) dpd[pidx] = acc;
    }
    __syncthreads();
    if (tid < WAYS*WAYS){
        int a = tid/WAYS, c = tid%WAYS;
        float d2 = fmaxf(dpd[a*WAYS+a] + dpd[c*WAYS+c] - 2.0f*dpd[tid], 0.0f);
        dpe[tid] = expf(-LAMv*d2);
    }
    __syncthreads();
    if (tid < WAYS){
        float q[WAYS]; float s = 0.0f;
        #pragma unroll
        for (int k=0;k<WAYS;k++){ q[k] = dpe[tid*WAYS+k] + 1e-12f; s += q[k]; }
        float H = 0.0f;
        #pragma unroll
        for (int k=0;k<WAYS;k++){ float pp = q[k]/s; H -= pp*logf(pp); }
        maskv[tid] = (H*INVLOG5 < omega_s) ? 1.0f : 0.0f;
    }
    __syncthreads();
    float* fwr = g_feat + (size_t)b*N105*DIM + (size_t)N100*DIM;
    for (int t=tid; t<WAYS*DIM; t+=256) fwr[t] = sp[t]*maskv[t/DIM];
    for (int t=tid; t<N100*WAYS; t+=256) Zb[t] = z[t/WAYS][t%WAYS];
    if (tid < WAYS*WAYS) Zb[N100*WAYS + tid] = dpe[tid]*maskv[tid/WAYS];
}

// ---- K4: strip + cached E100 -> A=I-aW -> LU solve (A X = Z) ----
__global__ void __launch_bounds__(256) k_graph_solve(){
    __shared__ float As[N105*N105];   // 44100 B; front also used as ap[5*640] temp
    __shared__ float st[N105*WAYS];   // strip dots; reused as colL in LU
    __shared__ float zz[N105*WAYS];
    __shared__ float nrm[N105];       // row norms; reused as dm
    int b = blockIdx.x, tid = threadIdx.x;
    int w = tid>>5, lane = tid&31;
    const float* fb = g_feat + (size_t)b*N105*DIM;

    // load masked protos (rows 100..104) into smem (temp space inside As)
    float* ap = As;
    for (int t=tid; t<WAYS*DIM; t+=256) ap[t] = fb[(size_t)N100*DIM + t];
    __syncthreads();

    // strip dots st[i][p] = f_i . ap_p, and norms nrm[i]
    for (int i=w; i<N105; i+=8){
        const float* f = fb + (size_t)i*DIM;
        float nf=0.f, dk[WAYS]={0,0,0,0,0};
        for (int d=lane; d<DIM; d+=32){
            float v = f[d];
            nf += v*v;
            #pragma unroll
            for (int p=0;p<WAYS;p++) dk[p] += v*ap[p*DIM+d];
        }
        nf = wredSum(nf);
        #pragma unroll
        for (int p=0;p<WAYS;p++) dk[p] = wredSum(dk[p]);
        if (lane==0){
            nrm[i] = nf;
            #pragma unroll
            for (int p=0;p<WAYS;p++) st[i*WAYS+p] = dk[p];
        }
    }
    __syncthreads();

    // assemble W into As (E100 cached block + fresh strip)
    const float* E = g_E100 + (size_t)b*N100*N100;
    for (int t=tid; t<N105*N105; t+=256){
        int i = t/N105, j = t - i*N105;
        float v;
        if (i < N100 && j < N100){
            v = E[i*N100+j];
        } else if (i == j){
            v = 0.0f;
        } else {
            float dot = (j >= N100) ? st[i*WAYS + (j-N100)] : st[j*WAYS + (i-N100)];
            float d2 = fmaxf(nrm[i] + nrm[j] - 2.0f*dot, 0.0f);
            v = expf(-LAMv*d2);
        }
        As[t] = v;
    }
    float* Zb = g_Z + (size_t)b*N105*WAYS;
    for (int t=tid; t<N105*WAYS; t+=256) zz[t] = Zb[t];
    __syncthreads();

    // dm = rsqrt(row sums)  (reuse nrm)
    if (tid < N105){
        float s = 0.0f;
        for (int j=0;j<N105;j++) s += As[tid*N105+j];
        nrm[tid] = rsqrtf(s);
    }
    __syncthreads();
    // A = I - 0.7 * dm_i dm_j W
    for (int t=tid; t<N105*N105; t+=256){
        int i = t/N105, j = t - i*N105;
        As[t] = ((i==j)?1.0f:0.0f) - 0.7f*nrm[i]*nrm[j]*As[t];
    }
    __syncthreads();

    // LU forward elimination, 2D rank-1 updates (A SPD, no pivoting)
    float* colL = st;
    for (int k=0;k<N105-1;k++){
        float invP = 1.0f/As[k*N105+k];
        for (int i=k+1+tid; i<N105; i+=256) colL[i] = As[i*N105+k]*invP;
        __syncthreads();
        int jb = k+1+lane;
        float pr[4];
        #pragma unroll
        for (int m=0;m<4;m++){ int j = jb+32*m; pr[m] = (j<N105)? As[k*N105+j] : 0.0f; }
        float pz = (lane<WAYS)? zz[k*WAYS+lane] : 0.0f;
        for (int i=k+1+w; i<N105; i+=8){
            float l = colL[i];
            #pragma unroll
            for (int m=0;m<4;m++){ int j = jb+32*m; if (j<N105) As[i*N105+j] -= l*pr[m]; }
            if (lane<WAYS) zz[i*WAYS+lane] -= l*pz;
        }
        __syncthreads();
    }
    // back substitution
    for (int k=N105-1;k>=0;k--){
        if (tid < WAYS) zz[k*WAYS+tid] /= As[k*N105+k];
        __syncthreads();
        for (int t=tid; t<k*WAYS; t+=256){
            int i=t/WAYS, m=t-i*WAYS;
            zz[i*WAYS+m] -= As[i*N105+k]*zz[k*WAYS+m];
        }
        __syncthreads();
    }
    for (int t=tid; t<N105*WAYS; t+=256) Zb[t] = zz[t];
}

// ---- K5: accuracy over queries ----
__global__ void __launch_bounds__(128) k_acc(const int* __restrict__ yq, float* __restrict__ out){
    __shared__ int cnt[128];
    int b = blockIdx.x, tid = threadIdx.x;
    int m = 0;
    if (tid < NQ){
        const float* zr = g_Z + ((size_t)b*N105 + NSUP + tid)*WAYS;
        float best = zr[0]; int bi = 0;
        #pragma unroll
        for (int k=1;k<WAYS;k++){ if (zr[k] > best){ best = zr[k]; bi = k; } }
        m = (bi == yq[b*NQ + tid]) ? 1 : 0;
    }
    cnt[tid] = m;
    __syncthreads();
    for (int s=64; s; s>>=1){ if (tid < s) cnt[tid] += cnt[tid+s]; __syncthreads(); }
    if (tid==0) out[b] = (float)cnt[0] / 75.0f;
}

extern "C" void kernel_launch(void* const* d_in, const int* in_sizes, int n_in,
                              void* d_out, int out_size){
    const float* xs = (const float*)d_in[0];
    const float* xq = (const float*)d_in[1];
    const int*   ys = (const int*)d_in[2];
    const int*   yq = (const int*)d_in[3];
    float* out = (float*)d_out;
    (void)in_sizes; (void)n_in; (void)out_size;

    k_init<<<RUNS,256>>>(xs, xq);
    k_gram0<<<RUNS,256>>>();
    for (int e=0;e<3;e++){
        k_dist_proto<<<RUNS,256>>>();
        k_sinkhorn<NQ,0><<<64,256>>>(ys, 2*e, 0);
        k_scan<<<1,256>>>(2*e);
        k_sinkhorn<NQ,0><<<64,256>>>(ys, 2*e, 1);
        k_update<<<RUNS,256>>>(ys);
        k_graph_solve<<<RUNS,256>>>();
        k_sinkhorn<N105,NSUP><<<64,256>>>(ys, 2*e+1, 0);
        k_scan<<<1,256>>>(2*e+1);
        k_sinkhorn<N105,NSUP><<<64,256>>>(ys, 2*e+1, 1);
    }
    k_acc<<<RUNS,128>>>(yq, out);
}